// round 11
// baseline (speedup 1.0000x reference)
#include <cuda_runtime.h>
#include <cstdint>
#include <math.h>

// Problem constants
#define T_    4
#define B_    32
#define N_    512
#define D_    256
#define H_    4
#define M_TOT (T_*B_*N_)          // 65536 rows
#define TPLANE (B_*N_*D_)         // 4194304 elements per timestep plane
#define BN_   (B_*N_)             // 16384
#define MASK_PER (T_*B_*N_*H_*2)  // 524288 uint32 words per spike tensor
#define FULLM 0xffffffffu

typedef unsigned long long ull;

// ---------------------------------------------------------------------------
// Scratch (device globals; no cudaMalloc allowed)
// ---------------------------------------------------------------------------
__device__ unsigned int g_masks[3][MASK_PER]; // q/k/v spike bitmasks (6 MiB)
__device__ float        g_attn[T_*TPLANE];    // attention output (t,b,n,D)
__device__ float        g_proj[T_*TPLANE];    // after wo projection

// ---------------------------------------------------------------------------
// Packed f32x2 helpers. fma.rn.f32x2: each 32-bit half is an IEEE-754 rn FMA,
// bit-identical to scalar fmaf.
// ---------------------------------------------------------------------------
#define FMA2(d, a, b) asm("fma.rn.f32x2 %0, %1, %2, %0;" : "+l"(d) : "l"(a), "l"(b))

__device__ __forceinline__ ull dup2(float x) {
    ull r; unsigned u = __float_as_uint(x);
    asm("mov.b64 %0, {%1, %1};" : "=l"(r) : "r"(u));
    return r;
}
__device__ __forceinline__ void unpack2(ull v, float& lo, float& hi) {
    unsigned a, b;
    asm("mov.b64 {%0, %1}, %2;" : "=r"(a), "=r"(b) : "l"(v));
    lo = __uint_as_float(a); hi = __uint_as_float(b);
}

// ---------------------------------------------------------------------------
// GEMM (NT): Ctile[128,256] = Atile[128,256] * W[256,256]^T, fp32 FFMA2.
// Row-pair packing: acc[i][j] holds rows (trow+2i, trow+2i+1) x col (lane*8+j).
// A pairs load free via LDS.64 from As[kc][row] (adjacent rows adjacent).
// B stored duplicated (w,w) with XOR swizzle (cg ^ (j<<2)) -> conflict-free
// LDS.64. Per-element k-chain: ascending serial FMA, bit-identical to R8/R9.
// 512 threads: warp w owns rows w*8..w*8+7; lane owns cols lane*8..lane*8+7.
// FUSE mode (q/k/v): tile rows are t-interleaved l = bn_off*4 + t so each
// thread holds complete PLIF chains; epilogue emits spike bitmasks directly.
// ---------------------------------------------------------------------------
template<bool FUSE>
__global__ __launch_bounds__(512, 1) void gemm512(const float* __restrict__ A,
                                                  const float* __restrict__ W,
                                                  float* __restrict__ C,
                                                  const float* __restrict__ wp,
                                                  unsigned int* __restrict__ masks) {
    extern __shared__ char smem[];
    float (*As)[16][128] = reinterpret_cast<float(*)[16][128]>(smem);          // 2x8KB
    ull   (*Ws)[4096]    = reinterpret_cast<ull(*)[4096]>(smem + 16384);       // 2x32KB

    const int tid  = threadIdx.x;
    const int warp = tid >> 5, lane = tid & 31;
    const int trow = warp * 8;
    const int bx   = blockIdx.x;

    // A loader: thread handles tile-row al = tid>>2, k-offset ak
    const int al = tid >> 2;
    const int ak = (tid & 3) * 4;
    const size_t arow = FUSE ? ((size_t)(al & 3) * BN_ + (size_t)bx * 32 + (al >> 2))
                             : ((size_t)bx * 128 + al);
    // W loader: thread handles W row wr, k-half wh
    const int wr = tid >> 1;
    const int wh = tid & 1;
    const int wj = wr & 7, wcg = wr >> 3;

    ull acc[4][8];
#pragma unroll
    for (int i = 0; i < 4; i++)
#pragma unroll
        for (int j = 0; j < 8; j++) acc[i][j] = 0ull;

    float4 pa, pw0, pw1;

#define LOADG(k0) do {                                                              \
        pa  = *reinterpret_cast<const float4*>(&A[arow * 256 + (k0) + ak]);         \
        pw0 = *reinterpret_cast<const float4*>(&W[(size_t)wr * 256 + (k0) + wh*8]); \
        pw1 = *reinterpret_cast<const float4*>(&W[(size_t)wr * 256 + (k0) + wh*8 + 4]); \
    } while (0)

#define STORES(buf) do {                                                            \
        As[buf][ak+0][al] = pa.x; As[buf][ak+1][al] = pa.y;                         \
        As[buf][ak+2][al] = pa.z; As[buf][ak+3][al] = pa.w;                         \
        float wv[8] = {pw0.x, pw0.y, pw0.z, pw0.w, pw1.x, pw1.y, pw1.z, pw1.w};     \
        _Pragma("unroll")                                                           \
        for (int q = 0; q < 8; q++) {                                               \
            int kc = wh * 8 + q;                                                    \
            Ws[buf][(kc * 8 + wj) * 32 + (wcg ^ (wj << 2))] = dup2(wv[q]);          \
        }                                                                           \
    } while (0)

    LOADG(0); STORES(0); __syncthreads();

    int buf = 0;
    for (int k0 = 0; k0 < 256; k0 += 16) {
        const bool more = (k0 + 16 < 256);
        if (more) LOADG(k0 + 16);
#pragma unroll
        for (int kk = 0; kk < 16; kk++) {
            const ull* ap = reinterpret_cast<const ull*>(&As[buf][kk][trow]);
            ull aa[4];
#pragma unroll
            for (int i = 0; i < 4; i++) aa[i] = ap[i];
            ull bb[8];
#pragma unroll
            for (int j = 0; j < 8; j++)
                bb[j] = Ws[buf][(kk * 8 + j) * 32 + (lane ^ (j << 2))];
#pragma unroll
            for (int i = 0; i < 4; i++)
#pragma unroll
                for (int j = 0; j < 8; j++) FMA2(acc[i][j], aa[i], bb[j]);
        }
        if (more) STORES(buf ^ 1);
        __syncthreads();
        buf ^= 1;
    }

    if (FUSE) {
        // PLIF over t (in-register chains) -> spike bitmask words.
        // acc[bo*2+tp][j]: lo half = t=2*tp, hi half = t=2*tp+1, bn = bx*32+warp*2+bo.
        // d = lane*8 + j; word dw = lane>>2, bit = (lane&3)*8 + j.
        const float decay = 1.f / (1.f + expf(-wp[0]));   // w=0 -> exactly 0.5
#pragma unroll
        for (int bo = 0; bo < 2; bo++) {
            const int bn = bx * 32 + warp * 2 + bo;
            unsigned bt[4] = {0u, 0u, 0u, 0u};
#pragma unroll
            for (int j = 0; j < 8; j++) {
                float uu[4];
                unpack2(acc[bo * 2 + 0][j], uu[0], uu[1]);
                unpack2(acc[bo * 2 + 1][j], uu[2], uu[3]);
                float v = 0.f;
#pragma unroll
                for (int t = 0; t < 4; t++) {
                    float h = __fadd_rn(v, __fmul_rn(__fsub_rn(uu[t], v), decay));
                    bool s = (h >= 1.0f);
                    bt[t] |= ((unsigned)s) << j;
                    v = s ? 0.f : h;
                }
            }
#pragma unroll
            for (int t = 0; t < 4; t++) {
                unsigned w32 = bt[t] << ((lane & 3) * 8);
                w32 |= __shfl_down_sync(FULLM, w32, 1);
                w32 |= __shfl_down_sync(FULLM, w32, 2);
                if ((lane & 3) == 0)
                    masks[((t * BN_ + bn) * 4 + (lane >> 3)) * 2 + ((lane >> 2) & 1)] = w32;
            }
        }
    } else {
#pragma unroll
        for (int i = 0; i < 4; i++) {
            float lo[8], hi[8];
#pragma unroll
            for (int j = 0; j < 8; j++) unpack2(acc[i][j], lo[j], hi[j]);
            size_t r0 = (size_t)(bx * 128 + trow + 2 * i) * 256 + lane * 8;
            *reinterpret_cast<float4*>(&C[r0])           = make_float4(lo[0], lo[1], lo[2], lo[3]);
            *reinterpret_cast<float4*>(&C[r0 + 4])       = make_float4(lo[4], lo[5], lo[6], lo[7]);
            *reinterpret_cast<float4*>(&C[r0 + 256])     = make_float4(hi[0], hi[1], hi[2], hi[3]);
            *reinterpret_cast<float4*>(&C[r0 + 256 + 4]) = make_float4(hi[4], hi[5], hi[6], hi[7]);
        }
    }
#undef LOADG
#undef STORES
}

// ---------------------------------------------------------------------------
// Fused attention per (t,b,h).  (UNCHANGED from R8 — bit-exact recipe)
// ---------------------------------------------------------------------------
__global__ __launch_bounds__(256) void attn_kernel(float* __restrict__ out) {
    const int tbh = blockIdx.x;
    const int h   = tbh & 3;
    const int tb  = tbh >> 2;              // t*32+b
    const int rowbase = blockIdx.y * 128;
    const int tid  = threadIdx.x;
    const int warp = tid >> 5;
    const int lane = tid & 31;

    __shared__ unsigned int klo[512], khi[512], vlo[512], vhi[512];
    __shared__ unsigned int vc[64][17];        // column-major v bits, padded
    __shared__ unsigned char dbuf[8][512];     // per-row (maxpc - pc) per m
    __shared__ float wtab[8][68];              // per-row 0.1*(LUT[d]/s)
    __shared__ float lut[65];                  // expf(-0.125*d)

    if (tid < 65) lut[tid] = expf(-0.125f * (float)tid);

    const unsigned int* qm = g_masks[0];
    const unsigned int* km = g_masks[1];
    const unsigned int* vm = g_masks[2];

    for (int n = tid; n < 512; n += 256) {
        int mi = ((tb * 512 + n) * 4 + h) * 2;
        klo[n] = km[mi]; khi[n] = km[mi + 1];
        vlo[n] = vm[mi]; vhi[n] = vm[mi + 1];
    }
    __syncthreads();

    // Transpose v bits into per-d columns via ballot
    for (int c = warp; c < 16; c += 8) {
        unsigned int wl = vlo[c * 32 + lane];
        unsigned int wh = vhi[c * 32 + lane];
#pragma unroll
        for (int dd = 0; dd < 32; dd++) {
            unsigned int b0 = __ballot_sync(FULLM, (wl >> dd) & 1u);
            unsigned int b1 = __ballot_sync(FULLM, (wh >> dd) & 1u);
            if (lane == dd) { vc[dd][c] = b0; vc[dd + 32][c] = b1; }
        }
    }
    __syncthreads();

    for (int it = 0; it < 16; it++) {
        int n  = rowbase + it * 8 + warp;
        int mi = ((tb * 512 + n) * 4 + h) * 2;
        unsigned int ql = qm[mi], qh = qm[mi + 1];

        // popcount logits (exact); row max (order-free on exact ints)
        int pc[16];
        int mx = 0;
#pragma unroll
        for (int j = 0; j < 16; j++) {
            int m = j * 32 + lane;
            pc[j] = __popc(ql & klo[m]) + __popc(qh & khi[m]);
            mx = max(mx, pc[j]);
        }
#pragma unroll
        for (int o = 16; o > 0; o >>= 1) mx = max(mx, __shfl_xor_sync(FULLM, mx, o));

        // exp values; per-simulated-warp shfl.down tree (XLA warp reduce)
        float p[16];
#pragma unroll
        for (int j = 0; j < 16; j++) {
            int dlt = mx - pc[j];
            dbuf[warp][j * 32 + lane] = (unsigned char)dlt;
            float v = lut[dlt];
            v = __fadd_rn(v, __shfl_down_sync(FULLM, v, 16));
            v = __fadd_rn(v, __shfl_down_sync(FULLM, v, 8));
            v = __fadd_rn(v, __shfl_down_sync(FULLM, v, 4));
            v = __fadd_rn(v, __shfl_down_sync(FULLM, v, 2));
            v = __fadd_rn(v, __shfl_down_sync(FULLM, v, 1));
            p[j] = __shfl_sync(FULLM, v, 0);   // warp-j partial, broadcast
        }
        // inter-warp combine: balanced down-tree over 16 partials (zero-padded
        // to 32 lanes in XLA -> offsets 16 add zeros exactly, then 8,4,2,1)
        float q0 = __fadd_rn(p[0], p[8]),  q1 = __fadd_rn(p[1], p[9]);
        float q2 = __fadd_rn(p[2], p[10]), q3 = __fadd_rn(p[3], p[11]);
        float q4 = __fadd_rn(p[4], p[12]), q5 = __fadd_rn(p[5], p[13]);
        float q6 = __fadd_rn(p[6], p[14]), q7 = __fadd_rn(p[7], p[15]);
        float r0 = __fadd_rn(q0, q4), r1 = __fadd_rn(q1, q5);
        float r2 = __fadd_rn(q2, q6), r3 = __fadd_rn(q3, q7);
        float s0 = __fadd_rn(r0, r2), s1 = __fadd_rn(r1, r3);
        float s  = __fadd_rn(s0, s1);

        // per-distinct-value attn_out = fl(0.1 * fl(e/s)) (reference order)
        for (int d = lane; d < 65; d += 32)
            wtab[warp][d] = __fmul_rn(0.1f, __fdiv_rn(lut[d], s));
        __syncwarp();

        // sparse attn @ v: ascending walk == serial ascending-m FMA
        float acc0 = 0.f, acc1 = 0.f;
        const int d0 = lane, d1 = lane + 32;
#pragma unroll 4
        for (int c = 0; c < 16; c++) {
            unsigned int w0 = vc[d0][c];
            unsigned int w1 = vc[d1][c];
            const unsigned char* db = &dbuf[warp][c * 32];
            while (w0) { int j = __ffs(w0) - 1; w0 &= w0 - 1; acc0 = __fadd_rn(acc0, wtab[warp][db[j]]); }
            while (w1) { int j = __ffs(w1) - 1; w1 &= w1 - 1; acc1 = __fadd_rn(acc1, wtab[warp][db[j]]); }
        }
        int ob = (tb * 512 + n) * 256 + h * 64;
        out[ob + d0] = acc0;
        out[ob + d1] = acc1;
        __syncwarp();
    }
}

// ---------------------------------------------------------------------------
// LayerNorm over D then final PLIF over T. (UNCHANGED from R8 — bit-exact)
// ---------------------------------------------------------------------------
__global__ __launch_bounds__(256) void ln_plif(const float* __restrict__ X,
                                               const float* __restrict__ gamma,
                                               const float* __restrict__ beta,
                                               const float* __restrict__ wp,
                                               float* __restrict__ out) {
    const int bn   = blockIdx.x;
    const int d    = threadIdx.x;
    const int lane = d & 31, warp = d >> 5;
    __shared__ float part[8];
    __shared__ float bcast;
    const float decay = 1.f / (1.f + expf(-wp[0]));   // exactly 0.5
    const float g  = gamma[d];
    const float be = beta[d];
    float v = 0.f;

#pragma unroll
    for (int t = 0; t < 4; t++) {
        float x = X[(size_t)t * TPLANE + (size_t)bn * 256 + d];

        // ---- mean: warp down-tree, then padded down-tree over 8 partials ----
        float sv = x;
        sv = __fadd_rn(sv, __shfl_down_sync(FULLM, sv, 16));
        sv = __fadd_rn(sv, __shfl_down_sync(FULLM, sv, 8));
        sv = __fadd_rn(sv, __shfl_down_sync(FULLM, sv, 4));
        sv = __fadd_rn(sv, __shfl_down_sync(FULLM, sv, 2));
        sv = __fadd_rn(sv, __shfl_down_sync(FULLM, sv, 1));
        if (lane == 0) part[warp] = sv;
        __syncthreads();
        if (warp == 0) {
            float pv = (lane < 8) ? part[lane] : 0.f;
            pv = __fadd_rn(pv, __shfl_down_sync(FULLM, pv, 16));  // +0 exact
            pv = __fadd_rn(pv, __shfl_down_sync(FULLM, pv, 8));   // +0 exact
            pv = __fadd_rn(pv, __shfl_down_sync(FULLM, pv, 4));
            pv = __fadd_rn(pv, __shfl_down_sync(FULLM, pv, 2));
            pv = __fadd_rn(pv, __shfl_down_sync(FULLM, pv, 1));
            if (lane == 0) bcast = __fmul_rn(pv, (1.f / 256.f));  // exact pow2
        }
        __syncthreads();
        float mu = bcast;
        __syncthreads();

        // ---- variance: same association over centered squares ----
        float c  = __fsub_rn(x, mu);
        float qv = __fmul_rn(c, c);
        qv = __fadd_rn(qv, __shfl_down_sync(FULLM, qv, 16));
        qv = __fadd_rn(qv, __shfl_down_sync(FULLM, qv, 8));
        qv = __fadd_rn(qv, __shfl_down_sync(FULLM, qv, 4));
        qv = __fadd_rn(qv, __shfl_down_sync(FULLM, qv, 2));
        qv = __fadd_rn(qv, __shfl_down_sync(FULLM, qv, 1));
        if (lane == 0) part[warp] = qv;
        __syncthreads();
        if (warp == 0) {
            float pv = (lane < 8) ? part[lane] : 0.f;
            pv = __fadd_rn(pv, __shfl_down_sync(FULLM, pv, 16));
            pv = __fadd_rn(pv, __shfl_down_sync(FULLM, pv, 8));
            pv = __fadd_rn(pv, __shfl_down_sync(FULLM, pv, 4));
            pv = __fadd_rn(pv, __shfl_down_sync(FULLM, pv, 2));
            pv = __fadd_rn(pv, __shfl_down_sync(FULLM, pv, 1));
            if (lane == 0) bcast = __fmul_rn(pv, (1.f / 256.f));
        }
        __syncthreads();
        float var = bcast;
        __syncthreads();

        float rs = rsqrtf(__fadd_rn(var, 1e-5f));
        float y  = __fadd_rn(__fmul_rn(__fmul_rn(c, rs), g), be);
        float hh = __fadd_rn(v, __fmul_rn(__fsub_rn(y, v), decay));
        bool sp = (hh >= 1.0f);
        out[(size_t)t * TPLANE + (size_t)bn * 256 + d] = sp ? 1.f : 0.f;
        v = sp ? 0.f : hh;
    }
}

// ---------------------------------------------------------------------------
extern "C" void kernel_launch(void* const* d_in, const int* in_sizes, int n_in,
                              void* d_out, int out_size) {
    const float* x     = (const float*)d_in[0];
    const float* wq    = (const float*)d_in[1];
    const float* wk    = (const float*)d_in[2];
    const float* wv    = (const float*)d_in[3];
    const float* wo    = (const float*)d_in[4];
    const float* gamma = (const float*)d_in[5];
    const float* beta  = (const float*)d_in[6];
    const float* w_q   = (const float*)d_in[7];
    const float* w_k   = (const float*)d_in[8];
    const float* w_v   = (const float*)d_in[9];
    // d_in[10] = w_attn: unused — attn PLIF provably never spikes (softmax < V_TH)
    const float* w_p   = (const float*)d_in[11];

    float* attn;  float* proj;  unsigned int* masks;
    cudaGetSymbolAddress((void**)&masks, g_masks);
    cudaGetSymbolAddress((void**)&attn,  g_attn);
    cudaGetSymbolAddress((void**)&proj,  g_proj);

    const int SMEMSZ = 16384 + 65536;   // 80 KB dynamic
    cudaFuncSetAttribute(gemm512<true>,  cudaFuncAttributeMaxDynamicSharedMemorySize, SMEMSZ);
    cudaFuncSetAttribute(gemm512<false>, cudaFuncAttributeMaxDynamicSharedMemorySize, SMEMSZ);

    // q/k/v GEMMs with fused PLIF -> spike bitmask epilogue (no g_y roundtrip)
    gemm512<true><<<M_TOT / 128, 512, SMEMSZ>>>(x, wq, nullptr, w_q, masks);
    gemm512<true><<<M_TOT / 128, 512, SMEMSZ>>>(x, wk, nullptr, w_k, masks + MASK_PER);
    gemm512<true><<<M_TOT / 128, 512, SMEMSZ>>>(x, wv, nullptr, w_v, masks + 2 * MASK_PER);

    // fused attention (popcount logits + XLA-tree softmax + sparse AV)
    attn_kernel<<<dim3(T_ * B_ * H_, 4), 256>>>(attn);

    // output projection (plain epilogue)
    gemm512<false><<<M_TOT / 128, 512, SMEMSZ>>>(attn, wo, proj, nullptr, nullptr);

    // LayerNorm + final PLIF -> d_out
    ln_plif<<<BN_, 256>>>(proj, gamma, beta, w_p, (float*)d_out);
}

// round 12
// speedup vs baseline: 1.0255x; 1.0255x over previous
#include <cuda_runtime.h>
#include <cstdint>
#include <math.h>

// Problem constants
#define T_    4
#define B_    32
#define N_    512
#define D_    256
#define H_    4
#define M_TOT (T_*B_*N_)          // 65536 rows
#define TPLANE (B_*N_*D_)         // 4194304 elements per timestep plane
#define PLANE (T_*TPLANE)         // 16777216 elements per full (T,B,N,D) tensor
#define BN_   (B_*N_)             // 16384
#define MASK_PER (T_*B_*N_*H_*2)  // 524288 uint32 words per spike tensor
#define FULLM 0xffffffffu

typedef unsigned long long ull;

// ---------------------------------------------------------------------------
// Scratch (device globals; no cudaMalloc allowed)
// ---------------------------------------------------------------------------
__device__ float        g_y[3][PLANE];        // pre-activation q/k/v (192 MiB)
__device__ unsigned int g_masks[3][MASK_PER]; // q/k/v spike bitmasks (6 MiB)
__device__ float        g_attn[PLANE];        // attention output (t,b,n,D)
__device__ float        g_proj[PLANE];        // after wo projection

// ---------------------------------------------------------------------------
// Packed f32x2 helpers. fma.rn.f32x2: each 32-bit half is an IEEE-754 rn FMA,
// bit-identical to scalar fmaf.
// ---------------------------------------------------------------------------
#define FMA2(d, a, b) asm("fma.rn.f32x2 %0, %1, %2, %0;" : "+l"(d) : "l"(a), "l"(b))

__device__ __forceinline__ ull dup2(float x) {
    ull r; unsigned u = __float_as_uint(x);
    asm("mov.b64 %0, {%1, %1};" : "=l"(r) : "r"(u));
    return r;
}
__device__ __forceinline__ void unpack2(ull v, float& lo, float& hi) {
    unsigned a, b;
    asm("mov.b64 {%0, %1}, %2;" : "=r"(a), "=r"(b) : "l"(v));
    lo = __uint_as_float(a); hi = __uint_as_float(b);
}

// ---------------------------------------------------------------------------
// SGEMM (NT) via packed FFMA2 (R9 version — proven fastest, bit-exact).
// C[M,256] = A[M,256] * W[256,256]^T. Per-element ascending-k serial FMA.
// Block tile 128x256, 256 threads, 8x16 per-thread (64 f32x2 accumulators).
// ---------------------------------------------------------------------------
__global__ __launch_bounds__(256, 1) void sgemm_f32x2(const float* __restrict__ A,
                                                      const float* __restrict__ W,
                                                      float* __restrict__ C) {
    __shared__ float As[2][16][128];               // [buf][kc][row]   (16KB)
    __shared__ ull   Ws2[2][2048];                 // [buf][(kc*8+j)*16 + c^S] (32KB)

    const int tid  = threadIdx.x;
    const int bm   = blockIdx.x * 128;
    const int trow = (tid >> 4) * 8;       // 0,8,..,120
    const int cgrp = tid & 15;             // column group: cols cgrp*16..+15
    const int lrow = tid >> 2;             // 0..63 (loader)
    const int lkc  = (tid & 3) * 4;        // 0,4,8,12 (loader k offset)

    ull acc[8][8];
#pragma unroll
    for (int i = 0; i < 8; i++)
#pragma unroll
        for (int j = 0; j < 8; j++) acc[i][j] = 0ull;

    float4 pa[2], pw[4];

#define LOAD_GLOBAL(k0)  do {                                                        \
        pa[0] = *reinterpret_cast<const float4*>(&A[(size_t)(bm + lrow)      * 256 + (k0) + lkc]); \
        pa[1] = *reinterpret_cast<const float4*>(&A[(size_t)(bm + lrow + 64) * 256 + (k0) + lkc]); \
        pw[0] = *reinterpret_cast<const float4*>(&W[(size_t)(lrow)       * 256 + (k0) + lkc]);     \
        pw[1] = *reinterpret_cast<const float4*>(&W[(size_t)(lrow + 64)  * 256 + (k0) + lkc]);     \
        pw[2] = *reinterpret_cast<const float4*>(&W[(size_t)(lrow + 128) * 256 + (k0) + lkc]);     \
        pw[3] = *reinterpret_cast<const float4*>(&W[(size_t)(lrow + 192) * 256 + (k0) + lkc]);     \
    } while (0)

#define STORE_SMEM(buf)  do {                                                        \
        float av[2][4] = {{pa[0].x, pa[0].y, pa[0].z, pa[0].w},                      \
                          {pa[1].x, pa[1].y, pa[1].z, pa[1].w}};                     \
        _Pragma("unroll")                                                            \
        for (int l = 0; l < 2; l++) {                                                \
            int row = lrow + 64 * l;                                                 \
            _Pragma("unroll")                                                        \
            for (int ko = 0; ko < 4; ko++) As[buf][lkc + ko][row] = av[l][ko];       \
        }                                                                            \
        float* wf = reinterpret_cast<float*>(&Ws2[buf][0]);                          \
        float wv[4][4] = {{pw[0].x, pw[0].y, pw[0].z, pw[0].w},                      \
                          {pw[1].x, pw[1].y, pw[1].z, pw[1].w},                      \
                          {pw[2].x, pw[2].y, pw[2].z, pw[2].w},                      \
                          {pw[3].x, pw[3].y, pw[3].z, pw[3].w}};                     \
        _Pragma("unroll")                                                            \
        for (int l = 0; l < 4; l++) {                                                \
            int n  = lrow + 64 * l;                                                  \
            int cc = n >> 4, jj = (n & 15) >> 1, hf = n & 1;                         \
            _Pragma("unroll")                                                        \
            for (int ko = 0; ko < 4; ko++) {                                         \
                int kc = lkc + ko;                                                   \
                int sw = cc ^ ((kc & 12) | (jj & 3));                                \
                wf[(((kc * 8 + jj) * 16 + sw) << 1) + hf] = wv[l][ko];               \
            }                                                                        \
        }                                                                            \
    } while (0)

    LOAD_GLOBAL(0);
    STORE_SMEM(0);
    __syncthreads();

    int buf = 0;
    for (int k0 = 0; k0 < 256; k0 += 16) {
        const bool more = (k0 + 16 < 256);
        if (more) LOAD_GLOBAL(k0 + 16);

#pragma unroll
        for (int kk = 0; kk < 16; kk++) {
            float4 a0 = *reinterpret_cast<const float4*>(&As[buf][kk][trow]);
            float4 a1 = *reinterpret_cast<const float4*>(&As[buf][kk][trow + 4]);
            ull aa[8];
            aa[0] = dup2(a0.x); aa[1] = dup2(a0.y); aa[2] = dup2(a0.z); aa[3] = dup2(a0.w);
            aa[4] = dup2(a1.x); aa[5] = dup2(a1.y); aa[6] = dup2(a1.z); aa[7] = dup2(a1.w);

            ull bb[8];
#pragma unroll
            for (int j = 0; j < 8; j++) {
                int sw = cgrp ^ ((kk & 12) | (j & 3));
                bb[j] = Ws2[buf][(kk * 8 + j) * 16 + sw];
            }
#pragma unroll
            for (int i = 0; i < 8; i++)
#pragma unroll
                for (int j = 0; j < 8; j++) FMA2(acc[i][j], aa[i], bb[j]);
        }

        if (more) STORE_SMEM(buf ^ 1);
        __syncthreads();
        buf ^= 1;
    }

#pragma unroll
    for (int i = 0; i < 8; i++) {
        float* cp = &C[(size_t)(bm + trow + i) * 256 + cgrp * 16];
#pragma unroll
        for (int t4 = 0; t4 < 4; t4++) {
            float4 o;
            unpack2(acc[i][2 * t4],     o.x, o.y);
            unpack2(acc[i][2 * t4 + 1], o.z, o.w);
            *reinterpret_cast<float4*>(cp + 4 * t4) = o;
        }
    }
#undef LOAD_GLOBAL
#undef STORE_SMEM
}

// ---------------------------------------------------------------------------
// PLIF over T for q/k/v pre-activations -> spike bitmasks. (R9, bit-exact)
// ---------------------------------------------------------------------------
__global__ __launch_bounds__(256) void plif_spikes(const float* __restrict__ y,
                                                   const float* __restrict__ wp,
                                                   unsigned int* __restrict__ masks) {
    const int bn   = blockIdx.x;
    const int d    = threadIdx.x;
    const int lane = d & 31;
    const float decay = 1.f / (1.f + expf(-wp[0]));   // w=0 -> exactly 0.5
    const int idx0 = bn * 256 + d;
    float v = 0.f;
#pragma unroll
    for (int t = 0; t < 4; t++) {
        float u = y[(size_t)t * TPLANE + idx0];
        float h = __fadd_rn(v, __fmul_rn(__fsub_rn(u, v), decay));
        bool s = (h >= 1.0f);
        v = s ? 0.f : h;
        unsigned int bal = __ballot_sync(FULLM, s);
        if (lane == 0) {
            int hh   = d >> 6;
            int word = (d >> 5) & 1;
            masks[((t * BN_ + bn) * H_ + hh) * 2 + word] = bal;
        }
    }
}

// ---------------------------------------------------------------------------
// Fused attention per (t,b,h). One block handles ALL 512 rows (no duplicated
// k/v load + transpose). Frozen bit-exact recipe:
//  - logits popc*0.125 exact; exp via lut (libdevice expf)
//  - softmax sum: per-simulated-warp shfl.down tree + balanced 16-partial tree
//  - per-element attn_out = fl(0.1 * fl(e/s)) via 65-entry wtab, expanded to
//    per-row pw[512] float table (single LDS per add on the walk)
//  - AV: ascending sparse bit-walk == serial ascending-m FMA chain
// Grid: 512 = (t*B+b)*H+h. 256 threads, warp per row, 64 row-iterations.
// ---------------------------------------------------------------------------
__global__ __launch_bounds__(256) void attn_kernel(float* __restrict__ out) {
    const int tbh = blockIdx.x;
    const int h   = tbh & 3;
    const int tb  = tbh >> 2;              // t*32+b
    const int tid  = threadIdx.x;
    const int warp = tid >> 5;
    const int lane = tid & 31;

    __shared__ unsigned int klo[512], khi[512], vlo[512], vhi[512];
    __shared__ unsigned int vc[64][17];        // column-major v bits, padded
    __shared__ float pw[8][512];               // per-row expanded weights
    __shared__ float wtab[8][68];              // per-row 0.1*(LUT[d]/s)
    __shared__ float lut[65];                  // expf(-0.125*d)

    if (tid < 65) lut[tid] = expf(-0.125f * (float)tid);

    const unsigned int* qm = g_masks[0];
    const unsigned int* km = g_masks[1];
    const unsigned int* vm = g_masks[2];

    for (int n = tid; n < 512; n += 256) {
        int mi = ((tb * 512 + n) * 4 + h) * 2;
        klo[n] = km[mi]; khi[n] = km[mi + 1];
        vlo[n] = vm[mi]; vhi[n] = vm[mi + 1];
    }
    __syncthreads();

    // Transpose v bits into per-d columns via ballot
    for (int c = warp; c < 16; c += 8) {
        unsigned int wl = vlo[c * 32 + lane];
        unsigned int wh = vhi[c * 32 + lane];
#pragma unroll
        for (int dd = 0; dd < 32; dd++) {
            unsigned int b0 = __ballot_sync(FULLM, (wl >> dd) & 1u);
            unsigned int b1 = __ballot_sync(FULLM, (wh >> dd) & 1u);
            if (lane == dd) { vc[dd][c] = b0; vc[dd + 32][c] = b1; }
        }
    }
    __syncthreads();

    for (int it = 0; it < 64; it++) {
        int n  = it * 8 + warp;
        int mi = ((tb * 512 + n) * 4 + h) * 2;
        unsigned int ql = qm[mi], qh = qm[mi + 1];

        // popcount logits (exact); row max (order-free on exact ints)
        int dlt[16];
        int mx = 0;
#pragma unroll
        for (int j = 0; j < 16; j++) {
            int m = j * 32 + lane;
            dlt[j] = __popc(ql & klo[m]) + __popc(qh & khi[m]);
            mx = max(mx, dlt[j]);
        }
#pragma unroll
        for (int o = 16; o > 0; o >>= 1) mx = max(mx, __shfl_xor_sync(FULLM, mx, o));

        // exp values; per-simulated-warp shfl.down tree (XLA warp reduce)
        float p[16];
#pragma unroll
        for (int j = 0; j < 16; j++) {
            dlt[j] = mx - dlt[j];
            float v = lut[dlt[j]];
            v = __fadd_rn(v, __shfl_down_sync(FULLM, v, 16));
            v = __fadd_rn(v, __shfl_down_sync(FULLM, v, 8));
            v = __fadd_rn(v, __shfl_down_sync(FULLM, v, 4));
            v = __fadd_rn(v, __shfl_down_sync(FULLM, v, 2));
            v = __fadd_rn(v, __shfl_down_sync(FULLM, v, 1));
            p[j] = __shfl_sync(FULLM, v, 0);   // warp-j partial, broadcast
        }
        // inter-warp combine: balanced down-tree over 16 partials (zero-padded
        // to 32 lanes in XLA -> offsets 16 add zeros exactly, then 8,4,2,1)
        float q0 = __fadd_rn(p[0], p[8]),  q1 = __fadd_rn(p[1], p[9]);
        float q2 = __fadd_rn(p[2], p[10]), q3 = __fadd_rn(p[3], p[11]);
        float q4 = __fadd_rn(p[4], p[12]), q5 = __fadd_rn(p[5], p[13]);
        float q6 = __fadd_rn(p[6], p[14]), q7 = __fadd_rn(p[7], p[15]);
        float r0 = __fadd_rn(q0, q4), r1 = __fadd_rn(q1, q5);
        float r2 = __fadd_rn(q2, q6), r3 = __fadd_rn(q3, q7);
        float s0 = __fadd_rn(r0, r2), s1 = __fadd_rn(r1, r3);
        float s  = __fadd_rn(s0, s1);

        // per-distinct-value attn_out = fl(0.1 * fl(e/s)) (reference order)
        for (int d = lane; d < 65; d += 32)
            wtab[warp][d] = __fmul_rn(0.1f, __fdiv_rn(lut[d], s));
        __syncwarp();

        // expand to per-row float table: one LDS per add on the walk
#pragma unroll
        for (int j = 0; j < 16; j++)
            pw[warp][j * 32 + lane] = wtab[warp][dlt[j]];
        __syncwarp();

        // sparse attn @ v: ascending walk == serial ascending-m FMA
        float acc0 = 0.f, acc1 = 0.f;
        const float* pp = pw[warp];
        const int d0 = lane, d1 = lane + 32;
#pragma unroll 4
        for (int c = 0; c < 16; c++) {
            unsigned int w0 = vc[d0][c];
            unsigned int w1 = vc[d1][c];
            const float* pc = pp + c * 32;
            while (w0) { int j = __ffs(w0) - 1; w0 &= w0 - 1; acc0 = __fadd_rn(acc0, pc[j]); }
            while (w1) { int j = __ffs(w1) - 1; w1 &= w1 - 1; acc1 = __fadd_rn(acc1, pc[j]); }
        }
        int ob = (tb * 512 + n) * 256 + h * 64;
        out[ob + d0] = acc0;
        out[ob + d1] = acc1;
        __syncwarp();
    }
}

// ---------------------------------------------------------------------------
// LayerNorm over D then final PLIF over T. (UNCHANGED from R8 — bit-exact)
// ---------------------------------------------------------------------------
__global__ __launch_bounds__(256) void ln_plif(const float* __restrict__ X,
                                               const float* __restrict__ gamma,
                                               const float* __restrict__ beta,
                                               const float* __restrict__ wp,
                                               float* __restrict__ out) {
    const int bn   = blockIdx.x;
    const int d    = threadIdx.x;
    const int lane = d & 31, warp = d >> 5;
    __shared__ float part[8];
    __shared__ float bcast;
    const float decay = 1.f / (1.f + expf(-wp[0]));   // exactly 0.5
    const float g  = gamma[d];
    const float be = beta[d];
    float v = 0.f;

#pragma unroll
    for (int t = 0; t < 4; t++) {
        float x = X[(size_t)t * TPLANE + (size_t)bn * 256 + d];

        // ---- mean: warp down-tree, then padded down-tree over 8 partials ----
        float sv = x;
        sv = __fadd_rn(sv, __shfl_down_sync(FULLM, sv, 16));
        sv = __fadd_rn(sv, __shfl_down_sync(FULLM, sv, 8));
        sv = __fadd_rn(sv, __shfl_down_sync(FULLM, sv, 4));
        sv = __fadd_rn(sv, __shfl_down_sync(FULLM, sv, 2));
        sv = __fadd_rn(sv, __shfl_down_sync(FULLM, sv, 1));
        if (lane == 0) part[warp] = sv;
        __syncthreads();
        if (warp == 0) {
            float pv = (lane < 8) ? part[lane] : 0.f;
            pv = __fadd_rn(pv, __shfl_down_sync(FULLM, pv, 16));  // +0 exact
            pv = __fadd_rn(pv, __shfl_down_sync(FULLM, pv, 8));   // +0 exact
            pv = __fadd_rn(pv, __shfl_down_sync(FULLM, pv, 4));
            pv = __fadd_rn(pv, __shfl_down_sync(FULLM, pv, 2));
            pv = __fadd_rn(pv, __shfl_down_sync(FULLM, pv, 1));
            if (lane == 0) bcast = __fmul_rn(pv, (1.f / 256.f));  // exact pow2
        }
        __syncthreads();
        float mu = bcast;
        __syncthreads();

        // ---- variance: same association over centered squares ----
        float c  = __fsub_rn(x, mu);
        float qv = __fmul_rn(c, c);
        qv = __fadd_rn(qv, __shfl_down_sync(FULLM, qv, 16));
        qv = __fadd_rn(qv, __shfl_down_sync(FULLM, qv, 8));
        qv = __fadd_rn(qv, __shfl_down_sync(FULLM, qv, 4));
        qv = __fadd_rn(qv, __shfl_down_sync(FULLM, qv, 2));
        qv = __fadd_rn(qv, __shfl_down_sync(FULLM, qv, 1));
        if (lane == 0) part[warp] = qv;
        __syncthreads();
        if (warp == 0) {
            float pv = (lane < 8) ? part[lane] : 0.f;
            pv = __fadd_rn(pv, __shfl_down_sync(FULLM, pv, 16));
            pv = __fadd_rn(pv, __shfl_down_sync(FULLM, pv, 8));
            pv = __fadd_rn(pv, __shfl_down_sync(FULLM, pv, 4));
            pv = __fadd_rn(pv, __shfl_down_sync(FULLM, pv, 2));
            pv = __fadd_rn(pv, __shfl_down_sync(FULLM, pv, 1));
            if (lane == 0) bcast = __fmul_rn(pv, (1.f / 256.f));
        }
        __syncthreads();
        float var = bcast;
        __syncthreads();

        float rs = rsqrtf(__fadd_rn(var, 1e-5f));
        float y  = __fadd_rn(__fmul_rn(__fmul_rn(c, rs), g), be);
        float hh = __fadd_rn(v, __fmul_rn(__fsub_rn(y, v), decay));
        bool sp = (hh >= 1.0f);
        out[(size_t)t * TPLANE + (size_t)bn * 256 + d] = sp ? 1.f : 0.f;
        v = sp ? 0.f : hh;
    }
}

// ---------------------------------------------------------------------------
extern "C" void kernel_launch(void* const* d_in, const int* in_sizes, int n_in,
                              void* d_out, int out_size) {
    const float* x     = (const float*)d_in[0];
    const float* wq    = (const float*)d_in[1];
    const float* wk    = (const float*)d_in[2];
    const float* wv    = (const float*)d_in[3];
    const float* wo    = (const float*)d_in[4];
    const float* gamma = (const float*)d_in[5];
    const float* beta  = (const float*)d_in[6];
    const float* w_q   = (const float*)d_in[7];
    const float* w_k   = (const float*)d_in[8];
    const float* w_v   = (const float*)d_in[9];
    // d_in[10] = w_attn: unused — attn PLIF provably never spikes (softmax < V_TH)
    const float* w_p   = (const float*)d_in[11];

    float* y;  float* attn;  float* proj;  unsigned int* masks;
    cudaGetSymbolAddress((void**)&y,     g_y);
    cudaGetSymbolAddress((void**)&masks, g_masks);
    cudaGetSymbolAddress((void**)&attn,  g_attn);
    cudaGetSymbolAddress((void**)&proj,  g_proj);

    // q/k/v pre-activation GEMMs (FFMA2, R9-proven)
    sgemm_f32x2<<<M_TOT / 128, 256>>>(x, wq, y);
    sgemm_f32x2<<<M_TOT / 128, 256>>>(x, wk, y + (size_t)PLANE);
    sgemm_f32x2<<<M_TOT / 128, 256>>>(x, wv, y + (size_t)2 * PLANE);

    // PLIF -> spike bitmasks
    plif_spikes<<<BN_, 256>>>(y,                    w_q, masks);
    plif_spikes<<<BN_, 256>>>(y + (size_t)PLANE,    w_k, masks + MASK_PER);
    plif_spikes<<<BN_, 256>>>(y + (size_t)2*PLANE,  w_v, masks + 2 * MASK_PER);

    // fused attention: one block per (t,b,h), all 512 rows
    attn_kernel<<<T_ * B_ * H_, 256>>>(attn);

    // output projection
    sgemm_f32x2<<<M_TOT / 128, 256>>>(attn, wo, proj);

    // LayerNorm + final PLIF -> d_out
    ln_plif<<<BN_, 256>>>(proj, gamma, beta, w_p, (float*)d_out);
}

// round 16
// speedup vs baseline: 1.2829x; 1.2510x over previous
#include <cuda_runtime.h>
#include <cstdint>
#include <math.h>

// Problem constants
#define T_    4
#define B_    32
#define N_    512
#define D_    256
#define H_    4
#define M_TOT (T_*B_*N_)          // 65536 rows
#define TPLANE (B_*N_*D_)         // 4194304 elements per timestep plane
#define PLANE (T_*TPLANE)         // 16777216 elements per full (T,B,N,D) tensor
#define BN_   (B_*N_)             // 16384
#define MASK_PER (T_*B_*N_*H_*2)  // 524288 uint32 words per spike tensor
#define FULLM 0xffffffffu

typedef unsigned long long ull;

// ---------------------------------------------------------------------------
// Scratch (device globals; no cudaMalloc allowed)
// ---------------------------------------------------------------------------
__device__ float        g_y[3][PLANE];        // pre-activation q/k/v (192 MiB)
__device__ unsigned int g_masks[3][MASK_PER]; // q/k/v spike bitmasks (6 MiB)
__device__ float        g_attn[PLANE];        // attention output (t,b,n,D)
__device__ float        g_proj[PLANE];        // after wo projection

// ---------------------------------------------------------------------------
// Packed f32x2 helpers. fma/add.rn.f32x2: each 32-bit half is an IEEE-754 rn
// op, bit-identical to the scalar instruction.
// ---------------------------------------------------------------------------
#define FMA2(d, a, b) asm("fma.rn.f32x2 %0, %1, %2, %0;" : "+l"(d) : "l"(a), "l"(b))
#define ADD2(a, b)    asm("add.rn.f32x2 %0, %0, %1;"     : "+l"(a) : "l"(b))

__device__ __forceinline__ ull dup2(float x) {
    ull r; unsigned u = __float_as_uint(x);
    asm("mov.b64 %0, {%1, %1};" : "=l"(r) : "r"(u));
    return r;
}
__device__ __forceinline__ ull pack2(float lo, float hi) {
    ull r;
    asm("mov.b64 %0, {%1, %2};" : "=l"(r) : "r"(__float_as_uint(lo)), "r"(__float_as_uint(hi)));
    return r;
}
__device__ __forceinline__ void unpack2(ull v, float& lo, float& hi) {
    unsigned a, b;
    asm("mov.b64 {%0, %1}, %2;" : "=r"(a), "=r"(b) : "l"(v));
    lo = __uint_as_float(a); hi = __uint_as_float(b);
}

// ---------------------------------------------------------------------------
// SGEMM (NT) via packed FFMA2 (R9 version — proven fastest, bit-exact).
// C[M,256] = A[M,256] * W[256,256]^T. Per-element ascending-k serial FMA.
// Block tile 128x256, 256 threads, 8x16 per-thread (64 f32x2 accumulators).
// ---------------------------------------------------------------------------
__global__ __launch_bounds__(256, 1) void sgemm_f32x2(const float* __restrict__ A,
                                                      const float* __restrict__ W,
                                                      float* __restrict__ C) {
    __shared__ float As[2][16][128];               // [buf][kc][row]   (16KB)
    __shared__ ull   Ws2[2][2048];                 // [buf][(kc*8+j)*16 + c^S] (32KB)

    const int tid  = threadIdx.x;
    const int bm   = blockIdx.x * 128;
    const int trow = (tid >> 4) * 8;       // 0,8,..,120
    const int cgrp = tid & 15;             // column group: cols cgrp*16..+15
    const int lrow = tid >> 2;             // 0..63 (loader)
    const int lkc  = (tid & 3) * 4;        // 0,4,8,12 (loader k offset)

    ull acc[8][8];
#pragma unroll
    for (int i = 0; i < 8; i++)
#pragma unroll
        for (int j = 0; j < 8; j++) acc[i][j] = 0ull;

    float4 pa[2], pw[4];

#define LOAD_GLOBAL(k0)  do {                                                        \
        pa[0] = *reinterpret_cast<const float4*>(&A[(size_t)(bm + lrow)      * 256 + (k0) + lkc]); \
        pa[1] = *reinterpret_cast<const float4*>(&A[(size_t)(bm + lrow + 64) * 256 + (k0) + lkc]); \
        pw[0] = *reinterpret_cast<const float4*>(&W[(size_t)(lrow)       * 256 + (k0) + lkc]);     \
        pw[1] = *reinterpret_cast<const float4*>(&W[(size_t)(lrow + 64)  * 256 + (k0) + lkc]);     \
        pw[2] = *reinterpret_cast<const float4*>(&W[(size_t)(lrow + 128) * 256 + (k0) + lkc]);     \
        pw[3] = *reinterpret_cast<const float4*>(&W[(size_t)(lrow + 192) * 256 + (k0) + lkc]);     \
    } while (0)

#define STORE_SMEM(buf)  do {                                                        \
        float av[2][4] = {{pa[0].x, pa[0].y, pa[0].z, pa[0].w},                      \
                          {pa[1].x, pa[1].y, pa[1].z, pa[1].w}};                     \
        _Pragma("unroll")                                                            \
        for (int l = 0; l < 2; l++) {                                                \
            int row = lrow + 64 * l;                                                 \
            _Pragma("unroll")                                                        \
            for (int ko = 0; ko < 4; ko++) As[buf][lkc + ko][row] = av[l][ko];       \
        }                                                                            \
        float* wf = reinterpret_cast<float*>(&Ws2[buf][0]);                          \
        float wv[4][4] = {{pw[0].x, pw[0].y, pw[0].z, pw[0].w},                      \
                          {pw[1].x, pw[1].y, pw[1].z, pw[1].w},                      \
                          {pw[2].x, pw[2].y, pw[2].z, pw[2].w},                      \
                          {pw[3].x, pw[3].y, pw[3].z, pw[3].w}};                     \
        _Pragma("unroll")                                                            \
        for (int l = 0; l < 4; l++) {                                                \
            int n  = lrow + 64 * l;                                                  \
            int cc = n >> 4, jj = (n & 15) >> 1, hf = n & 1;                         \
            _Pragma("unroll")                                                        \
            for (int ko = 0; ko < 4; ko++) {                                         \
                int kc = lkc + ko;                                                   \
                int sw = cc ^ ((kc & 12) | (jj & 3));                                \
                wf[(((kc * 8 + jj) * 16 + sw) << 1) + hf] = wv[l][ko];               \
            }                                                                        \
        }                                                                            \
    } while (0)

    LOAD_GLOBAL(0);
    STORE_SMEM(0);
    __syncthreads();

    int buf = 0;
    for (int k0 = 0; k0 < 256; k0 += 16) {
        const bool more = (k0 + 16 < 256);
        if (more) LOAD_GLOBAL(k0 + 16);

#pragma unroll
        for (int kk = 0; kk < 16; kk++) {
            float4 a0 = *reinterpret_cast<const float4*>(&As[buf][kk][trow]);
            float4 a1 = *reinterpret_cast<const float4*>(&As[buf][kk][trow + 4]);
            ull aa[8];
            aa[0] = dup2(a0.x); aa[1] = dup2(a0.y); aa[2] = dup2(a0.z); aa[3] = dup2(a0.w);
            aa[4] = dup2(a1.x); aa[5] = dup2(a1.y); aa[6] = dup2(a1.z); aa[7] = dup2(a1.w);

            ull bb[8];
#pragma unroll
            for (int j = 0; j < 8; j++) {
                int sw = cgrp ^ ((kk & 12) | (j & 3));
                bb[j] = Ws2[buf][(kk * 8 + j) * 16 + sw];
            }
#pragma unroll
            for (int i = 0; i < 8; i++)
#pragma unroll
                for (int j = 0; j < 8; j++) FMA2(acc[i][j], aa[i], bb[j]);
        }

        if (more) STORE_SMEM(buf ^ 1);
        __syncthreads();
        buf ^= 1;
    }

#pragma unroll
    for (int i = 0; i < 8; i++) {
        float* cp = &C[(size_t)(bm + trow + i) * 256 + cgrp * 16];
#pragma unroll
        for (int t4 = 0; t4 < 4; t4++) {
            float4 o;
            unpack2(acc[i][2 * t4],     o.x, o.y);
            unpack2(acc[i][2 * t4 + 1], o.z, o.w);
            *reinterpret_cast<float4*>(cp + 4 * t4) = o;
        }
    }
#undef LOAD_GLOBAL
#undef STORE_SMEM
}

// ---------------------------------------------------------------------------
// PLIF over T for q/k/v pre-activations -> spike bitmasks. (R9, bit-exact)
// ---------------------------------------------------------------------------
__global__ __launch_bounds__(256) void plif_spikes(const float* __restrict__ y,
                                                   const float* __restrict__ wp,
                                                   unsigned int* __restrict__ masks) {
    const int bn   = blockIdx.x;
    const int d    = threadIdx.x;
    const int lane = d & 31;
    const float decay = 1.f / (1.f + expf(-wp[0]));   // w=0 -> exactly 0.5
    const int idx0 = bn * 256 + d;
    float v = 0.f;
#pragma unroll
    for (int t = 0; t < 4; t++) {
        float u = y[(size_t)t * TPLANE + idx0];
        float h = __fadd_rn(v, __fmul_rn(__fsub_rn(u, v), decay));
        bool s = (h >= 1.0f);
        v = s ? 0.f : h;
        unsigned int bal = __ballot_sync(FULLM, s);
        if (lane == 0) {
            int hh   = d >> 6;
            int word = (d >> 5) & 1;
            masks[((t * BN_ + bn) * H_ + hh) * 2 + word] = bal;
        }
    }
}

// ---------------------------------------------------------------------------
// Fused attention per (t,b,h), ROW-PAIR FADD2 walk.
// Grid (512, 4): x=(t*B+b)*H+h, y=row-block of 128. 256 threads, 8 warps.
// Each warp handles a PAIR of adjacent rows per iteration (8 iterations).
// The v bit-pattern per d-column is row-independent, so one add.rn.f32x2
// performs both rows' adds for a set bit; weights pre-packed (w_n0, w_n1) in
// smem -> 1 LDS.64 + 1 FADD2 per set bit for 2 element-adds.
// All per-element FP chains (softmax trees, fl(0.1*fl(e/s)), ascending-m AV
// adds) are bitwise UNCHANGED from the R8/R9 recipe.
// ---------------------------------------------------------------------------
__global__ __launch_bounds__(256) void attn_kernel(float* __restrict__ out) {
    const int tbh = blockIdx.x;
    const int h   = tbh & 3;
    const int tb  = tbh >> 2;              // t*32+b
    const int rowbase = blockIdx.y * 128;
    const int tid  = threadIdx.x;
    const int warp = tid >> 5;
    const int lane = tid & 31;

    __shared__ unsigned int klo[512], khi[512];
    __shared__ unsigned int vc[64][17];        // column-major v bits, padded
    __shared__ float wt0[8][68], wt1[8][68];   // per-row 0.1*(LUT[d]/s)
    __shared__ float lut[65];                  // expf(-0.125*d)
    __shared__ ull pw2[8][512];                // packed (w_n0[m], w_n1[m])  32KB
    // v staging aliases into pw2 (dead after transpose, fenced by syncthreads)
    unsigned int* vlo = reinterpret_cast<unsigned int*>(&pw2[0][0]);
    unsigned int* vhi = vlo + 512;

    if (tid < 65) lut[tid] = expf(-0.125f * (float)tid);

    const unsigned int* qm = g_masks[0];
    const unsigned int* km = g_masks[1];
    const unsigned int* vm = g_masks[2];

    for (int n = tid; n < 512; n += 256) {
        int mi = ((tb * 512 + n) * 4 + h) * 2;
        klo[n] = km[mi]; khi[n] = km[mi + 1];
        vlo[n] = vm[mi]; vhi[n] = vm[mi + 1];
    }
    __syncthreads();

    // Transpose v bits into per-d columns via ballot
    for (int c = warp; c < 16; c += 8) {
        unsigned int wl = vlo[c * 32 + lane];
        unsigned int wh = vhi[c * 32 + lane];
#pragma unroll
        for (int dd = 0; dd < 32; dd++) {
            unsigned int b0 = __ballot_sync(FULLM, (wl >> dd) & 1u);
            unsigned int b1 = __ballot_sync(FULLM, (wh >> dd) & 1u);
            if (lane == dd) { vc[dd][c] = b0; vc[dd + 32][c] = b1; }
        }
    }
    __syncthreads();   // vlo/vhi dead; pw2 region free for reuse

    for (int it = 0; it < 8; it++) {
        const int n0 = rowbase + (it * 8 + warp) * 2;   // rows n0, n0+1
        int dlt0[16], dlt1[16];
        float sA, sB;

        // ---- per-row softmax (frozen R8 recipe), rows n0 and n0+1 ----
#pragma unroll
        for (int rr = 0; rr < 2; rr++) {
            int* dlt = rr ? dlt1 : dlt0;
            int mi = ((tb * 512 + n0 + rr) * 4 + h) * 2;
            unsigned int ql = qm[mi], qh = qm[mi + 1];
            int mx = 0;
#pragma unroll
            for (int j = 0; j < 16; j++) {
                int m = j * 32 + lane;
                dlt[j] = __popc(ql & klo[m]) + __popc(qh & khi[m]);
                mx = max(mx, dlt[j]);
            }
#pragma unroll
            for (int o = 16; o > 0; o >>= 1) mx = max(mx, __shfl_xor_sync(FULLM, mx, o));

            float p[16];
#pragma unroll
            for (int j = 0; j < 16; j++) {
                dlt[j] = mx - dlt[j];
                float v = lut[dlt[j]];
                v = __fadd_rn(v, __shfl_down_sync(FULLM, v, 16));
                v = __fadd_rn(v, __shfl_down_sync(FULLM, v, 8));
                v = __fadd_rn(v, __shfl_down_sync(FULLM, v, 4));
                v = __fadd_rn(v, __shfl_down_sync(FULLM, v, 2));
                v = __fadd_rn(v, __shfl_down_sync(FULLM, v, 1));
                p[j] = __shfl_sync(FULLM, v, 0);
            }
            float q0 = __fadd_rn(p[0], p[8]),  q1 = __fadd_rn(p[1], p[9]);
            float q2 = __fadd_rn(p[2], p[10]), q3 = __fadd_rn(p[3], p[11]);
            float q4 = __fadd_rn(p[4], p[12]), q5 = __fadd_rn(p[5], p[13]);
            float q6 = __fadd_rn(p[6], p[14]), q7 = __fadd_rn(p[7], p[15]);
            float r0 = __fadd_rn(q0, q4), r1 = __fadd_rn(q1, q5);
            float r2 = __fadd_rn(q2, q6), r3 = __fadd_rn(q3, q7);
            float s0 = __fadd_rn(r0, r2), s1 = __fadd_rn(r1, r3);
            float s  = __fadd_rn(s0, s1);
            if (rr) sB = s; else sA = s;
        }

        // per-distinct-value attn_out = fl(0.1 * fl(e/s)) per row
        for (int d = lane; d < 65; d += 32) {
            wt0[warp][d] = __fmul_rn(0.1f, __fdiv_rn(lut[d], sA));
            wt1[warp][d] = __fmul_rn(0.1f, __fdiv_rn(lut[d], sB));
        }
        __syncwarp();

        // pack per-m weight pairs (w_n0[m], w_n1[m])
#pragma unroll
        for (int j = 0; j < 16; j++)
            pw2[warp][j * 32 + lane] = pack2(wt0[warp][dlt0[j]], wt1[warp][dlt1[j]]);
        __syncwarp();

        // sparse attn @ v: ascending walk, FADD2 = both rows per set bit
        ull acc0 = 0ull, acc1 = 0ull;
        const ull* pp = pw2[warp];
        const int d0 = lane, d1 = lane + 32;
#pragma unroll 4
        for (int c = 0; c < 16; c++) {
            unsigned int w0 = vc[d0][c];
            unsigned int w1 = vc[d1][c];
            const ull* pc = pp + c * 32;
            while (w0) { int j = __ffs(w0) - 1; w0 &= w0 - 1; ADD2(acc0, pc[j]); }
            while (w1) { int j = __ffs(w1) - 1; w1 &= w1 - 1; ADD2(acc1, pc[j]); }
        }
        float a0lo, a0hi, a1lo, a1hi;
        unpack2(acc0, a0lo, a0hi);     // (row n0, row n0+1) for column d0
        unpack2(acc1, a1lo, a1hi);     // (row n0, row n0+1) for column d1
        size_t ob = (size_t)(tb * 512 + n0) * 256 + h * 64;
        out[ob + d0]       = a0lo;
        out[ob + d1]       = a1lo;
        out[ob + 256 + d0] = a0hi;
        out[ob + 256 + d1] = a1hi;
        __syncwarp();
    }
}

// ---------------------------------------------------------------------------
// LayerNorm over D then final PLIF over T. (UNCHANGED from R8 — bit-exact)
// ---------------------------------------------------------------------------
__global__ __launch_bounds__(256) void ln_plif(const float* __restrict__ X,
                                               const float* __restrict__ gamma,
                                               const float* __restrict__ beta,
                                               const float* __restrict__ wp,
                                               float* __restrict__ out) {
    const int bn   = blockIdx.x;
    const int d    = threadIdx.x;
    const int lane = d & 31, warp = d >> 5;
    __shared__ float part[8];
    __shared__ float bcast;
    const float decay = 1.f / (1.f + expf(-wp[0]));   // exactly 0.5
    const float g  = gamma[d];
    const float be = beta[d];
    float v = 0.f;

#pragma unroll
    for (int t = 0; t < 4; t++) {
        float x = X[(size_t)t * TPLANE + (size_t)bn * 256 + d];

        // ---- mean: warp down-tree, then padded down-tree over 8 partials ----
        float sv = x;
        sv = __fadd_rn(sv, __shfl_down_sync(FULLM, sv, 16));
        sv = __fadd_rn(sv, __shfl_down_sync(FULLM, sv, 8));
        sv = __fadd_rn(sv, __shfl_down_sync(FULLM, sv, 4));
        sv = __fadd_rn(sv, __shfl_down_sync(FULLM, sv, 2));
        sv = __fadd_rn(sv, __shfl_down_sync(FULLM, sv, 1));
        if (lane == 0) part[warp] = sv;
        __syncthreads();
        if (warp == 0) {
            float pv = (lane < 8) ? part[lane] : 0.f;
            pv = __fadd_rn(pv, __shfl_down_sync(FULLM, pv, 16));  // +0 exact
            pv = __fadd_rn(pv, __shfl_down_sync(FULLM, pv, 8));   // +0 exact
            pv = __fadd_rn(pv, __shfl_down_sync(FULLM, pv, 4));
            pv = __fadd_rn(pv, __shfl_down_sync(FULLM, pv, 2));
            pv = __fadd_rn(pv, __shfl_down_sync(FULLM, pv, 1));
            if (lane == 0) bcast = __fmul_rn(pv, (1.f / 256.f));  // exact pow2
        }
        __syncthreads();
        float mu = bcast;
        __syncthreads();

        // ---- variance: same association over centered squares ----
        float c  = __fsub_rn(x, mu);
        float qv = __fmul_rn(c, c);
        qv = __fadd_rn(qv, __shfl_down_sync(FULLM, qv, 16));
        qv = __fadd_rn(qv, __shfl_down_sync(FULLM, qv, 8));
        qv = __fadd_rn(qv, __shfl_down_sync(FULLM, qv, 4));
        qv = __fadd_rn(qv, __shfl_down_sync(FULLM, qv, 2));
        qv = __fadd_rn(qv, __shfl_down_sync(FULLM, qv, 1));
        if (lane == 0) part[warp] = qv;
        __syncthreads();
        if (warp == 0) {
            float pv = (lane < 8) ? part[lane] : 0.f;
            pv = __fadd_rn(pv, __shfl_down_sync(FULLM, pv, 16));
            pv = __fadd_rn(pv, __shfl_down_sync(FULLM, pv, 8));
            pv = __fadd_rn(pv, __shfl_down_sync(FULLM, pv, 4));
            pv = __fadd_rn(pv, __shfl_down_sync(FULLM, pv, 2));
            pv = __fadd_rn(pv, __shfl_down_sync(FULLM, pv, 1));
            if (lane == 0) bcast = __fmul_rn(pv, (1.f / 256.f));
        }
        __syncthreads();
        float var = bcast;
        __syncthreads();

        float rs = rsqrtf(__fadd_rn(var, 1e-5f));
        float y  = __fadd_rn(__fmul_rn(__fmul_rn(c, rs), g), be);
        float hh = __fadd_rn(v, __fmul_rn(__fsub_rn(y, v), decay));
        bool sp = (hh >= 1.0f);
        out[(size_t)t * TPLANE + (size_t)bn * 256 + d] = sp ? 1.f : 0.f;
        v = sp ? 0.f : hh;
    }
}

// ---------------------------------------------------------------------------
extern "C" void kernel_launch(void* const* d_in, const int* in_sizes, int n_in,
                              void* d_out, int out_size) {
    const float* x     = (const float*)d_in[0];
    const float* wq    = (const float*)d_in[1];
    const float* wk    = (const float*)d_in[2];
    const float* wv    = (const float*)d_in[3];
    const float* wo    = (const float*)d_in[4];
    const float* gamma = (const float*)d_in[5];
    const float* beta  = (const float*)d_in[6];
    const float* w_q   = (const float*)d_in[7];
    const float* w_k   = (const float*)d_in[8];
    const float* w_v   = (const float*)d_in[9];
    // d_in[10] = w_attn: unused — attn PLIF provably never spikes (softmax < V_TH)
    const float* w_p   = (const float*)d_in[11];

    float* y;  float* attn;  float* proj;  unsigned int* masks;
    cudaGetSymbolAddress((void**)&y,     g_y);
    cudaGetSymbolAddress((void**)&masks, g_masks);
    cudaGetSymbolAddress((void**)&attn,  g_attn);
    cudaGetSymbolAddress((void**)&proj,  g_proj);

    // q/k/v pre-activation GEMMs (FFMA2, R9-proven)
    sgemm_f32x2<<<M_TOT / 128, 256>>>(x, wq, y);
    sgemm_f32x2<<<M_TOT / 128, 256>>>(x, wk, y + (size_t)PLANE);
    sgemm_f32x2<<<M_TOT / 128, 256>>>(x, wv, y + (size_t)2 * PLANE);

    // PLIF -> spike bitmasks
    plif_spikes<<<BN_, 256>>>(y,                    w_q, masks);
    plif_spikes<<<BN_, 256>>>(y + (size_t)PLANE,    w_k, masks + MASK_PER);
    plif_spikes<<<BN_, 256>>>(y + (size_t)2*PLANE,  w_v, masks + 2 * MASK_PER);

    // fused attention: row-pair FADD2 walk, 2048 blocks
    attn_kernel<<<dim3(T_ * B_ * H_, 4), 256>>>(attn);

    // output projection
    sgemm_f32x2<<<M_TOT / 128, 256>>>(attn, wo, proj);

    // LayerNorm + final PLIF -> d_out
    ln_plif<<<BN_, 256>>>(proj, gamma, beta, w_p, (float*)d_out);
}

// round 17
// speedup vs baseline: 1.3487x; 1.0513x over previous
#include <cuda_runtime.h>
#include <cstdint>
#include <math.h>

// Problem constants
#define T_    4
#define B_    32
#define N_    512
#define D_    256
#define H_    4
#define M_TOT (T_*B_*N_)          // 65536 rows
#define TPLANE (B_*N_*D_)         // 4194304 elements per timestep plane
#define PLANE (T_*TPLANE)         // 16777216 elements per full (T,B,N,D) tensor
#define BN_   (B_*N_)             // 16384
#define MASK_PER (T_*B_*N_*H_*2)  // 524288 uint32 words per spike tensor
#define FULLM 0xffffffffu

typedef unsigned long long ull;

// ---------------------------------------------------------------------------
// Scratch (device globals; no cudaMalloc allowed)
// ---------------------------------------------------------------------------
__device__ float        g_y[3][PLANE];        // pre-activation q/k/v (192 MiB)
__device__ unsigned int g_masks[3][MASK_PER]; // q/k/v spike bitmasks (6 MiB)
__device__ float        g_attn[PLANE];        // attention output (t,b,n,D)
__device__ float        g_proj[PLANE];        // after wo projection

// ---------------------------------------------------------------------------
// Packed f32x2 helpers. fma/add.rn.f32x2: each 32-bit half is an IEEE-754 rn
// op, bit-identical to the scalar instruction.
// ---------------------------------------------------------------------------
#define FMA2(d, a, b) asm("fma.rn.f32x2 %0, %1, %2, %0;" : "+l"(d) : "l"(a), "l"(b))
#define ADD2(a, b)    asm("add.rn.f32x2 %0, %0, %1;"     : "+l"(a) : "l"(b))

__device__ __forceinline__ ull dup2(float x) {
    ull r; unsigned u = __float_as_uint(x);
    asm("mov.b64 %0, {%1, %1};" : "=l"(r) : "r"(u));
    return r;
}
__device__ __forceinline__ ull pack2(float lo, float hi) {
    ull r;
    asm("mov.b64 %0, {%1, %2};" : "=l"(r) : "r"(__float_as_uint(lo)), "r"(__float_as_uint(hi)));
    return r;
}
__device__ __forceinline__ void unpack2(ull v, float& lo, float& hi) {
    unsigned a, b;
    asm("mov.b64 {%0, %1}, %2;" : "=r"(a), "=r"(b) : "l"(v));
    lo = __uint_as_float(a); hi = __uint_as_float(b);
}

// ---------------------------------------------------------------------------
// SGEMM (NT) via packed FFMA2 (R9-proven body, bit-exact).
// Grid.y selects W/output plane: merged q/k/v in one launch (fewer wave tails).
// C[M,256] = A[M,256] * W[256,256]^T. Per-element ascending-k serial FMA.
// ---------------------------------------------------------------------------
__global__ __launch_bounds__(256, 1) void sgemm_f32x2(const float* __restrict__ A,
                                                      const float* __restrict__ W0,
                                                      const float* __restrict__ W1,
                                                      const float* __restrict__ W2,
                                                      float* __restrict__ C) {
    __shared__ float As[2][16][128];               // [buf][kc][row]   (16KB)
    __shared__ ull   Ws2[2][2048];                 // [buf][(kc*8+j)*16 + c^S] (32KB)

    const float* W = (blockIdx.y == 0) ? W0 : (blockIdx.y == 1) ? W1 : W2;
    float* Cb = C + (size_t)blockIdx.y * PLANE;

    const int tid  = threadIdx.x;
    const int bm   = blockIdx.x * 128;
    const int trow = (tid >> 4) * 8;       // 0,8,..,120
    const int cgrp = tid & 15;             // column group: cols cgrp*16..+15
    const int lrow = tid >> 2;             // 0..63 (loader)
    const int lkc  = (tid & 3) * 4;        // 0,4,8,12 (loader k offset)

    ull acc[8][8];
#pragma unroll
    for (int i = 0; i < 8; i++)
#pragma unroll
        for (int j = 0; j < 8; j++) acc[i][j] = 0ull;

    float4 pa[2], pw[4];

#define LOAD_GLOBAL(k0)  do {                                                        \
        pa[0] = *reinterpret_cast<const float4*>(&A[(size_t)(bm + lrow)      * 256 + (k0) + lkc]); \
        pa[1] = *reinterpret_cast<const float4*>(&A[(size_t)(bm + lrow + 64) * 256 + (k0) + lkc]); \
        pw[0] = *reinterpret_cast<const float4*>(&W[(size_t)(lrow)       * 256 + (k0) + lkc]);     \
        pw[1] = *reinterpret_cast<const float4*>(&W[(size_t)(lrow + 64)  * 256 + (k0) + lkc]);     \
        pw[2] = *reinterpret_cast<const float4*>(&W[(size_t)(lrow + 128) * 256 + (k0) + lkc]);     \
        pw[3] = *reinterpret_cast<const float4*>(&W[(size_t)(lrow + 192) * 256 + (k0) + lkc]);     \
    } while (0)

#define STORE_SMEM(buf)  do {                                                        \
        float av[2][4] = {{pa[0].x, pa[0].y, pa[0].z, pa[0].w},                      \
                          {pa[1].x, pa[1].y, pa[1].z, pa[1].w}};                     \
        _Pragma("unroll")                                                            \
        for (int l = 0; l < 2; l++) {                                                \
            int row = lrow + 64 * l;                                                 \
            _Pragma("unroll")                                                        \
            for (int ko = 0; ko < 4; ko++) As[buf][lkc + ko][row] = av[l][ko];       \
        }                                                                            \
        float* wf = reinterpret_cast<float*>(&Ws2[buf][0]);                          \
        float wv[4][4] = {{pw[0].x, pw[0].y, pw[0].z, pw[0].w},                      \
                          {pw[1].x, pw[1].y, pw[1].z, pw[1].w},                      \
                          {pw[2].x, pw[2].y, pw[2].z, pw[2].w},                      \
                          {pw[3].x, pw[3].y, pw[3].z, pw[3].w}};                     \
        _Pragma("unroll")                                                            \
        for (int l = 0; l < 4; l++) {                                                \
            int n  = lrow + 64 * l;                                                  \
            int cc = n >> 4, jj = (n & 15) >> 1, hf = n & 1;                         \
            _Pragma("unroll")                                                        \
            for (int ko = 0; ko < 4; ko++) {                                         \
                int kc = lkc + ko;                                                   \
                int sw = cc ^ ((kc & 12) | (jj & 3));                                \
                wf[(((kc * 8 + jj) * 16 + sw) << 1) + hf] = wv[l][ko];               \
            }                                                                        \
        }                                                                            \
    } while (0)

    LOAD_GLOBAL(0);
    STORE_SMEM(0);
    __syncthreads();

    int buf = 0;
    for (int k0 = 0; k0 < 256; k0 += 16) {
        const bool more = (k0 + 16 < 256);
        if (more) LOAD_GLOBAL(k0 + 16);

#pragma unroll
        for (int kk = 0; kk < 16; kk++) {
            float4 a0 = *reinterpret_cast<const float4*>(&As[buf][kk][trow]);
            float4 a1 = *reinterpret_cast<const float4*>(&As[buf][kk][trow + 4]);
            ull aa[8];
            aa[0] = dup2(a0.x); aa[1] = dup2(a0.y); aa[2] = dup2(a0.z); aa[3] = dup2(a0.w);
            aa[4] = dup2(a1.x); aa[5] = dup2(a1.y); aa[6] = dup2(a1.z); aa[7] = dup2(a1.w);

            ull bb[8];
#pragma unroll
            for (int j = 0; j < 8; j++) {
                int sw = cgrp ^ ((kk & 12) | (j & 3));
                bb[j] = Ws2[buf][(kk * 8 + j) * 16 + sw];
            }
#pragma unroll
            for (int i = 0; i < 8; i++)
#pragma unroll
                for (int j = 0; j < 8; j++) FMA2(acc[i][j], aa[i], bb[j]);
        }

        if (more) STORE_SMEM(buf ^ 1);
        __syncthreads();
        buf ^= 1;
    }

#pragma unroll
    for (int i = 0; i < 8; i++) {
        float* cp = &Cb[(size_t)(bm + trow + i) * 256 + cgrp * 16];
#pragma unroll
        for (int t4 = 0; t4 < 4; t4++) {
            float4 o;
            unpack2(acc[i][2 * t4],     o.x, o.y);
            unpack2(acc[i][2 * t4 + 1], o.z, o.w);
            *reinterpret_cast<float4*>(cp + 4 * t4) = o;
        }
    }
#undef LOAD_GLOBAL
#undef STORE_SMEM
}

// ---------------------------------------------------------------------------
// PLIF over T for q/k/v pre-activations -> spike bitmasks. (bit-exact)
// Merged: grid.y = tensor index (0=q,1=k,2=v).
// ---------------------------------------------------------------------------
__global__ __launch_bounds__(256) void plif_spikes(const float* __restrict__ y,
                                                   const float* __restrict__ wpq,
                                                   const float* __restrict__ wpk,
                                                   const float* __restrict__ wpv,
                                                   unsigned int* __restrict__ masks) {
    const int bn   = blockIdx.x;
    const int d    = threadIdx.x;
    const int lane = d & 31;
    const float* wp = (blockIdx.y == 0) ? wpq : (blockIdx.y == 1) ? wpk : wpv;
    const float* yb = y + (size_t)blockIdx.y * PLANE;
    unsigned int* mb = masks + (size_t)blockIdx.y * MASK_PER;

    const float decay = 1.f / (1.f + expf(-wp[0]));   // w=0 -> exactly 0.5
    const int idx0 = bn * 256 + d;
    float v = 0.f;
#pragma unroll
    for (int t = 0; t < 4; t++) {
        float u = yb[(size_t)t * TPLANE + idx0];
        float h = __fadd_rn(v, __fmul_rn(__fsub_rn(u, v), decay));
        bool s = (h >= 1.0f);
        v = s ? 0.f : h;
        unsigned int bal = __ballot_sync(FULLM, s);
        if (lane == 0) {
            int hh   = d >> 6;
            int word = (d >> 5) & 1;
            mb[((t * BN_ + bn) * H_ + hh) * 2 + word] = bal;
        }
    }
}

// ---------------------------------------------------------------------------
// Fused attention per (t,b,h), ROW-QUAD walk (LDS.128 + 2x FADD2).
// Grid (512, 4): x=(t*B+b)*H+h, y=row-block of 128. 256 threads, 8 warps.
// Each warp handles FOUR adjacent rows per iteration (4 iterations).
// Weight table pw: ulonglong2 per m = ((w_n0,w_n1),(w_n2,w_n3)) -> one
// LDS.128 + 2 ADD2 per set bit serves 4 element-adds.
// All per-element FP chains (softmax trees, fl(0.1*fl(e/s)), ascending-m AV
// adds) are bitwise UNCHANGED from the frozen R8 recipe.
// ---------------------------------------------------------------------------
__global__ __launch_bounds__(256) void attn_kernel(float* __restrict__ out) {
    const int tbh = blockIdx.x;
    const int h   = tbh & 3;
    const int tb  = tbh >> 2;              // t*32+b
    const int rowbase = blockIdx.y * 128;
    const int tid  = threadIdx.x;
    const int warp = tid >> 5;
    const int lane = tid & 31;

    __shared__ unsigned int klo[512], khi[512];
    __shared__ unsigned int vc[64][17];        // column-major v bits, padded
    __shared__ float wtA[8][68], wtB[8][68];   // per-row-pair 0.1*(LUT[d]/s)
    __shared__ float lut[65];                  // expf(-0.125*d)
    extern __shared__ ull pw[];                // [8][1024]: 2 ulls per m (64KB)
    // v staging aliases into pw (dead after transpose, fenced by syncthreads)
    unsigned int* vlo = reinterpret_cast<unsigned int*>(pw);
    unsigned int* vhi = vlo + 512;

    if (tid < 65) lut[tid] = expf(-0.125f * (float)tid);

    const unsigned int* qm = g_masks[0];
    const unsigned int* km = g_masks[1];
    const unsigned int* vm = g_masks[2];

    for (int n = tid; n < 512; n += 256) {
        int mi = ((tb * 512 + n) * 4 + h) * 2;
        klo[n] = km[mi]; khi[n] = km[mi + 1];
        vlo[n] = vm[mi]; vhi[n] = vm[mi + 1];
    }
    __syncthreads();

    // Transpose v bits into per-d columns via ballot
    for (int c = warp; c < 16; c += 8) {
        unsigned int wl = vlo[c * 32 + lane];
        unsigned int wh = vhi[c * 32 + lane];
#pragma unroll
        for (int dd = 0; dd < 32; dd++) {
            unsigned int b0 = __ballot_sync(FULLM, (wl >> dd) & 1u);
            unsigned int b1 = __ballot_sync(FULLM, (wh >> dd) & 1u);
            if (lane == dd) { vc[dd][c] = b0; vc[dd + 32][c] = b1; }
        }
    }
    __syncthreads();   // vlo/vhi dead; pw region free for reuse

    ull* mypw = pw + warp * 1024;

    for (int it = 0; it < 4; it++) {
        const int n0 = rowbase + (it * 8 + warp) * 4;   // rows n0..n0+3

        // ---- two row-pairs: softmax (frozen recipe) + pack weights ----
#pragma unroll
        for (int pr = 0; pr < 2; pr++) {
            int dltA_[16], dltB_[16];
            float sA, sB;
#pragma unroll
            for (int rr = 0; rr < 2; rr++) {
                int* dlt = rr ? dltB_ : dltA_;
                int mi = ((tb * 512 + n0 + pr * 2 + rr) * 4 + h) * 2;
                unsigned int ql = qm[mi], qh = qm[mi + 1];
                int mx = 0;
#pragma unroll
                for (int j = 0; j < 16; j++) {
                    int m = j * 32 + lane;
                    dlt[j] = __popc(ql & klo[m]) + __popc(qh & khi[m]);
                    mx = max(mx, dlt[j]);
                }
#pragma unroll
                for (int o = 16; o > 0; o >>= 1) mx = max(mx, __shfl_xor_sync(FULLM, mx, o));

                float p[16];
#pragma unroll
                for (int j = 0; j < 16; j++) {
                    dlt[j] = mx - dlt[j];
                    float v = lut[dlt[j]];
                    v = __fadd_rn(v, __shfl_down_sync(FULLM, v, 16));
                    v = __fadd_rn(v, __shfl_down_sync(FULLM, v, 8));
                    v = __fadd_rn(v, __shfl_down_sync(FULLM, v, 4));
                    v = __fadd_rn(v, __shfl_down_sync(FULLM, v, 2));
                    v = __fadd_rn(v, __shfl_down_sync(FULLM, v, 1));
                    p[j] = __shfl_sync(FULLM, v, 0);
                }
                float q0 = __fadd_rn(p[0], p[8]),  q1 = __fadd_rn(p[1], p[9]);
                float q2 = __fadd_rn(p[2], p[10]), q3 = __fadd_rn(p[3], p[11]);
                float q4 = __fadd_rn(p[4], p[12]), q5 = __fadd_rn(p[5], p[13]);
                float q6 = __fadd_rn(p[6], p[14]), q7 = __fadd_rn(p[7], p[15]);
                float r0 = __fadd_rn(q0, q4), r1 = __fadd_rn(q1, q5);
                float r2 = __fadd_rn(q2, q6), r3 = __fadd_rn(q3, q7);
                float s0 = __fadd_rn(r0, r2), s1 = __fadd_rn(r1, r3);
                float s  = __fadd_rn(s0, s1);
                if (rr) sB = s; else sA = s;
            }

            // per-distinct-value attn_out = fl(0.1 * fl(e/s)) per row
            for (int d = lane; d < 65; d += 32) {
                wtA[warp][d] = __fmul_rn(0.1f, __fdiv_rn(lut[d], sA));
                wtB[warp][d] = __fmul_rn(0.1f, __fdiv_rn(lut[d], sB));
            }
            __syncwarp();

            // pack weight pairs for this row-pair into half 'pr' of each entry
#pragma unroll
            for (int j = 0; j < 16; j++) {
                int m = j * 32 + lane;
                mypw[2 * m + pr] = pack2(wtA[warp][dltA_[j]], wtB[warp][dltB_[j]]);
            }
            __syncwarp();
        }

        // ---- sparse attn @ v: ascending walk, LDS.128 + 2x ADD2 = 4 rows ----
        ull a0a = 0ull, a0b = 0ull, a1a = 0ull, a1b = 0ull;
        const int d0 = lane, d1 = lane + 32;
#pragma unroll 4
        for (int c = 0; c < 16; c++) {
            unsigned int w0 = vc[d0][c];
            unsigned int w1 = vc[d1][c];
            const ull* pc = mypw + c * 64;       // 2 ulls per m, 32 m per c
            while (w0) {
                int j = __ffs(w0) - 1; w0 &= w0 - 1;
                ulonglong2 v = *reinterpret_cast<const ulonglong2*>(pc + 2 * j);
                ADD2(a0a, v.x); ADD2(a0b, v.y);
            }
            while (w1) {
                int j = __ffs(w1) - 1; w1 &= w1 - 1;
                ulonglong2 v = *reinterpret_cast<const ulonglong2*>(pc + 2 * j);
                ADD2(a1a, v.x); ADD2(a1b, v.y);
            }
        }
        float r0d0, r1d0, r2d0, r3d0, r0d1, r1d1, r2d1, r3d1;
        unpack2(a0a, r0d0, r1d0); unpack2(a0b, r2d0, r3d0);
        unpack2(a1a, r0d1, r1d1); unpack2(a1b, r2d1, r3d1);
        size_t ob = (size_t)(tb * 512 + n0) * 256 + h * 64;
        out[ob + d0]        = r0d0;  out[ob + d1]        = r0d1;
        out[ob + 256 + d0]  = r1d0;  out[ob + 256 + d1]  = r1d1;
        out[ob + 512 + d0]  = r2d0;  out[ob + 512 + d1]  = r2d1;
        out[ob + 768 + d0]  = r3d0;  out[ob + 768 + d1]  = r3d1;
        __syncwarp();
    }
}

// ---------------------------------------------------------------------------
// LayerNorm over D then final PLIF over T. (UNCHANGED from R8 — bit-exact)
// ---------------------------------------------------------------------------
__global__ __launch_bounds__(256) void ln_plif(const float* __restrict__ X,
                                               const float* __restrict__ gamma,
                                               const float* __restrict__ beta,
                                               const float* __restrict__ wp,
                                               float* __restrict__ out) {
    const int bn   = blockIdx.x;
    const int d    = threadIdx.x;
    const int lane = d & 31, warp = d >> 5;
    __shared__ float part[8];
    __shared__ float bcast;
    const float decay = 1.f / (1.f + expf(-wp[0]));   // exactly 0.5
    const float g  = gamma[d];
    const float be = beta[d];
    float v = 0.f;

#pragma unroll
    for (int t = 0; t < 4; t++) {
        float x = X[(size_t)t * TPLANE + (size_t)bn * 256 + d];

        // ---- mean: warp down-tree, then padded down-tree over 8 partials ----
        float sv = x;
        sv = __fadd_rn(sv, __shfl_down_sync(FULLM, sv, 16));
        sv = __fadd_rn(sv, __shfl_down_sync(FULLM, sv, 8));
        sv = __fadd_rn(sv, __shfl_down_sync(FULLM, sv, 4));
        sv = __fadd_rn(sv, __shfl_down_sync(FULLM, sv, 2));
        sv = __fadd_rn(sv, __shfl_down_sync(FULLM, sv, 1));
        if (lane == 0) part[warp] = sv;
        __syncthreads();
        if (warp == 0) {
            float pv = (lane < 8) ? part[lane] : 0.f;
            pv = __fadd_rn(pv, __shfl_down_sync(FULLM, pv, 16));  // +0 exact
            pv = __fadd_rn(pv, __shfl_down_sync(FULLM, pv, 8));   // +0 exact
            pv = __fadd_rn(pv, __shfl_down_sync(FULLM, pv, 4));
            pv = __fadd_rn(pv, __shfl_down_sync(FULLM, pv, 2));
            pv = __fadd_rn(pv, __shfl_down_sync(FULLM, pv, 1));
            if (lane == 0) bcast = __fmul_rn(pv, (1.f / 256.f));  // exact pow2
        }
        __syncthreads();
        float mu = bcast;
        __syncthreads();

        // ---- variance: same association over centered squares ----
        float c  = __fsub_rn(x, mu);
        float qv = __fmul_rn(c, c);
        qv = __fadd_rn(qv, __shfl_down_sync(FULLM, qv, 16));
        qv = __fadd_rn(qv, __shfl_down_sync(FULLM, qv, 8));
        qv = __fadd_rn(qv, __shfl_down_sync(FULLM, qv, 4));
        qv = __fadd_rn(qv, __shfl_down_sync(FULLM, qv, 2));
        qv = __fadd_rn(qv, __shfl_down_sync(FULLM, qv, 1));
        if (lane == 0) part[warp] = qv;
        __syncthreads();
        if (warp == 0) {
            float pv = (lane < 8) ? part[lane] : 0.f;
            pv = __fadd_rn(pv, __shfl_down_sync(FULLM, pv, 16));
            pv = __fadd_rn(pv, __shfl_down_sync(FULLM, pv, 8));
            pv = __fadd_rn(pv, __shfl_down_sync(FULLM, pv, 4));
            pv = __fadd_rn(pv, __shfl_down_sync(FULLM, pv, 2));
            pv = __fadd_rn(pv, __shfl_down_sync(FULLM, pv, 1));
            if (lane == 0) bcast = __fmul_rn(pv, (1.f / 256.f));
        }
        __syncthreads();
        float var = bcast;
        __syncthreads();

        float rs = rsqrtf(__fadd_rn(var, 1e-5f));
        float y  = __fadd_rn(__fmul_rn(__fmul_rn(c, rs), g), be);
        float hh = __fadd_rn(v, __fmul_rn(__fsub_rn(y, v), decay));
        bool sp = (hh >= 1.0f);
        out[(size_t)t * TPLANE + (size_t)bn * 256 + d] = sp ? 1.f : 0.f;
        v = sp ? 0.f : hh;
    }
}

// ---------------------------------------------------------------------------
extern "C" void kernel_launch(void* const* d_in, const int* in_sizes, int n_in,
                              void* d_out, int out_size) {
    const float* x     = (const float*)d_in[0];
    const float* wq    = (const float*)d_in[1];
    const float* wk    = (const float*)d_in[2];
    const float* wv    = (const float*)d_in[3];
    const float* wo    = (const float*)d_in[4];
    const float* gamma = (const float*)d_in[5];
    const float* beta  = (const float*)d_in[6];
    const float* w_q   = (const float*)d_in[7];
    const float* w_k   = (const float*)d_in[8];
    const float* w_v   = (const float*)d_in[9];
    // d_in[10] = w_attn: unused — attn PLIF provably never spikes (softmax < V_TH)
    const float* w_p   = (const float*)d_in[11];

    float* y;  float* attn;  float* proj;  unsigned int* masks;
    cudaGetSymbolAddress((void**)&y,     g_y);
    cudaGetSymbolAddress((void**)&masks, g_masks);
    cudaGetSymbolAddress((void**)&attn,  g_attn);
    cudaGetSymbolAddress((void**)&proj,  g_proj);

    static bool attr_set = false;
    if (!attr_set) {
        cudaFuncSetAttribute(attn_kernel, cudaFuncAttributeMaxDynamicSharedMemorySize, 65536);
        attr_set = true;
    }

    // q/k/v pre-activation GEMMs in ONE launch (grid.y = tensor)
    sgemm_f32x2<<<dim3(M_TOT / 128, 3), 256>>>(x, wq, wk, wv, y);

    // PLIF -> spike bitmasks (merged, grid.y = tensor)
    plif_spikes<<<dim3(BN_, 3), 256>>>(y, w_q, w_k, w_v, masks);

    // fused attention: row-quad LDS.128 walk, 2048 blocks
    attn_kernel<<<dim3(T_ * B_ * H_, 4), 256, 65536>>>(attn);

    // output projection
    sgemm_f32x2<<<dim3(M_TOT / 128, 1), 256>>>(attn, wo, wo, wo, proj);

    // LayerNorm + final PLIF -> d_out
    ln_plif<<<BN_, 256>>>(proj, gamma, beta, w_p, (float*)d_out);
}